// round 4
// baseline (speedup 1.0000x reference)
#include <cuda_runtime.h>
#include <cuda_bf16.h>
#include <cstdint>

#define IN_F   4096
#define OUT_F  768
#define BITS   6144
#define BATCH  1024

#define BM 128
#define BN 64
#define BK 64
#define NCHUNK (IN_F / BK)     // 64
#define NSTAGE 4
#define NCTA   ((BATCH / BM) * (OUT_F / BN))   // 8*12 = 96
#define DSMEM_BYTES (NSTAGE * (BM + BN) * BK * 2 + 256)

// ---------------- device scratch ----------------
__device__ __nv_bfloat16 g_wT[(size_t)OUT_F * IN_F];   // int_weights^T [768][4096]
__device__ __nv_bfloat16 g_lat[(size_t)BATCH * IN_F];  // latent bf16
__device__ float g_reg_part[3072];
__device__ float g_recon_part[NCTA];
__device__ int   g_ticket;

// ---------------- helpers ----------------
__device__ __forceinline__ float tanh_fast(float x) {
    float y; asm("tanh.approx.f32 %0, %1;" : "=f"(y) : "f"(x)); return y;
}
__device__ __forceinline__ uint32_t cvta_s(const void* p) {
    return (uint32_t)__cvta_generic_to_shared(p);
}
#define CP_ASYNC16(s, g) asm volatile("cp.async.cg.shared.global [%0], [%1], 16;\n" :: "r"(s), "l"(g))
#define CP_COMMIT        asm volatile("cp.async.commit_group;\n" ::: "memory")
#define CP_WAIT0         asm volatile("cp.async.wait_group 0;\n" ::: "memory")
#define CP_WAIT1         asm volatile("cp.async.wait_group 1;\n" ::: "memory")
#define CP_WAIT2         asm volatile("cp.async.wait_group 2;\n" ::: "memory")
#define LDSM4(r0, r1, r2, r3, a) \
    asm volatile("ldmatrix.sync.aligned.m8n8.x4.shared.b16 {%0,%1,%2,%3}, [%4];\n" \
                 : "=r"(r0), "=r"(r1), "=r"(r2), "=r"(r3) : "r"(a))
#define MMA(d, a, b0, b1) \
    asm volatile("mma.sync.aligned.m16n8k16.row.col.f32.bf16.bf16.f32 " \
                 "{%0,%1,%2,%3},{%4,%5,%6,%7},{%8,%9},{%0,%1,%2,%3};\n" \
                 : "+f"(d[0]), "+f"(d[1]), "+f"(d[2]), "+f"(d[3]) \
                 : "r"(a[0]), "r"(a[1]), "r"(a[2]), "r"(a[3]), "r"(b0), "r"(b1))

// ---------------- kernels ----------------

// sigmoid(weight) -> reg partials + int_weights^T bf16
__global__ void k_weights(const float* __restrict__ w) {
    __shared__ float s_iw[32][33];
    __shared__ float s_red[8];
    const float pw[8] = {1.f, 2.f, 4.f, 8.f, 16.f, 32.f, 64.f, -128.f};

    int k0 = blockIdx.x * 32;   // 128 blocks
    int n0 = blockIdx.y * 32;   // 24 blocks
    int t = threadIdx.x;

    float regloc = 0.f;
#pragma unroll
    for (int i = 0; i < 4; i++) {
        int c = t + i * 256;
        int kk = c >> 5, nn = c & 31;
        const float4* p = reinterpret_cast<const float4*>(
            w + (size_t)(k0 + kk) * BITS + (size_t)(n0 + nn) * 8);
        float4 w0 = p[0], w1 = p[1];
        float xs[8] = {w0.x, w0.y, w0.z, w0.w, w1.x, w1.y, w1.z, w1.w};
        float iw = 0.f;
#pragma unroll
        for (int b = 0; b < 8; b++) {
            float th = tanh_fast(0.5f * xs[b]);      // sigmoid = 0.5 + 0.5*th
            iw = fmaf(0.5f + 0.5f * th, pw[b], iw);
            regloc += 0.5f - 0.5f * fabsf(th);       // min(p, 1-p)
        }
        s_iw[kk][nn] = iw;
    }
    __syncthreads();
#pragma unroll
    for (int i = 0; i < 4; i++) {
        int c = t + i * 256;
        int nn = c >> 5, kk = c & 31;
        g_wT[(size_t)(n0 + nn) * IN_F + (k0 + kk)] = __float2bfloat16(s_iw[kk][nn]);
    }
#pragma unroll
    for (int o = 16; o > 0; o >>= 1)
        regloc += __shfl_xor_sync(0xffffffffu, regloc, o);
    if ((t & 31) == 0) s_red[t >> 5] = regloc;
    __syncthreads();
    if (t == 0) {
        float s = 0.f;
#pragma unroll
        for (int i = 0; i < 8; i++) s += s_red[i];
        g_reg_part[blockIdx.y * 128 + blockIdx.x] = s;
    }
}

// latent fp32 -> bf16
__global__ void k_convA(const float* __restrict__ lat) {
    int i = blockIdx.x * blockDim.x + threadIdx.x;
    int stride = gridDim.x * blockDim.x;
    const float4* src = reinterpret_cast<const float4*>(lat);
    __nv_bfloat162* o = reinterpret_cast<__nv_bfloat162*>(g_lat);
    float4 v[4];
#pragma unroll
    for (int j = 0; j < 4; j++) v[j] = src[i + j * stride];
#pragma unroll
    for (int j = 0; j < 4; j++) {
        int idx = i + j * stride;
        o[2 * idx]     = __floats2bfloat162_rn(v[j].x, v[j].y);
        o[2 * idx + 1] = __floats2bfloat162_rn(v[j].z, v[j].w);
    }
}

// int_sum(r,n)/255 on the fly from true_sum
__device__ __forceinline__ float tval(const float* __restrict__ ts, int r, int n) {
    const float4* p = reinterpret_cast<const float4*>(ts + ((size_t)r * OUT_F + n) * 8);
    float4 a = p[0], b = p[1];
    return (a.x + 2.f * a.y + 4.f * a.z + 8.f * a.w
            + 16.f * b.x + 32.f * b.y + 64.f * b.z - 128.f * b.w) * (1.0f / 255.0f);
}

// chunk loader: A 4x16B (row t>>1), B 2x16B (row t>>2), SW128-XOR swizzle
__device__ __forceinline__ void load_chunk(
    uint16_t* Asb, uint16_t* Bsb,
    const __nv_bfloat16* gA, const __nv_bfloat16* gB, int kbase, int t)
{
    int rowa = t >> 1, cb4 = (t & 1) * 4;
    int rowb = t >> 2, cb2 = (t & 3) * 2;
#pragma unroll
    for (int j = 0; j < 4; j++) {
        int c = cb4 + j;
        int sw = (c ^ (rowa & 7)) << 3;
        CP_ASYNC16(cvta_s(Asb + rowa * BK + sw), gA + (size_t)rowa * IN_F + kbase + c * 8);
    }
#pragma unroll
    for (int j = 0; j < 2; j++) {
        int c = cb2 + j;
        int sw = (c ^ (rowb & 7)) << 3;
        CP_ASYNC16(cvta_s(Bsb + rowb * BK + sw), gB + (size_t)rowb * IN_F + kbase + c * 8);
    }
}

// GEMM (ldmatrix+mma.sync, 4-stage cp.async) + fused loss + last-CTA final reduce
__global__ void __launch_bounds__(256, 1)
k_gemm_loss(const float* __restrict__ ts, float* __restrict__ out, int out_size) {
    extern __shared__ __align__(16) uint8_t dsm[];
    uint16_t* As = (uint16_t*)dsm;                       // NSTAGE * 128*64
    uint16_t* Bs = As + NSTAGE * BM * BK;                // NSTAGE * 64*64

    __shared__ float s_red[8], s_red2[8];
    __shared__ int s_last;

    int t = threadIdx.x, wid = t >> 5, lane = t & 31;
    int wm = wid & 3, wn = wid >> 2;                     // 4 M-warps x 2 N-warps
    int m0 = blockIdx.y * BM, n0 = blockIdx.x * BN;

    const __nv_bfloat16* gA = g_lat + (size_t)m0 * IN_F;
    const __nv_bfloat16* gB = g_wT + (size_t)n0 * IN_F;

    float acc[2][4][4] = {};    // [mt][nt][c]  warp tile 32x32

    // ldmatrix lane addressing (row, chunk-part)
    int la15 = lane & 15, la7 = lane & 7;
    int kadd = lane >> 4;                    // A: +0/+1 chunk
    int browq = ((lane >> 4) << 3) + la7;    // B rows: 0-7,0-7,8-15,8-15
    int kbdd = (lane >> 3) & 1;              // B: +0/+1/+0/+1 chunk

    // prologue: prefetch stages 0..2
    load_chunk(As, Bs, gA, gB, 0, t); CP_COMMIT;
    load_chunk(As + BM * BK, Bs + BN * BK, gA, gB, BK, t); CP_COMMIT;
    load_chunk(As + 2 * BM * BK, Bs + 2 * BN * BK, gA, gB, 2 * BK, t); CP_COMMIT;

    for (int kc = 0; kc < NCHUNK; kc++) {
        if (kc < NCHUNK - 2)      { CP_WAIT2; }
        else if (kc == NCHUNK - 2){ CP_WAIT1; }
        else                      { CP_WAIT0; }
        __syncthreads();

        if (kc + 3 < NCHUNK) {
            int b3 = (kc + 3) & (NSTAGE - 1);
            load_chunk(As + b3 * BM * BK, Bs + b3 * BN * BK, gA, gB, (kc + 3) * BK, t);
            CP_COMMIT;
        }

        const uint16_t* Ab = As + (kc & (NSTAGE - 1)) * BM * BK;
        const uint16_t* Bb = Bs + (kc & (NSTAGE - 1)) * BN * BK;

#pragma unroll
        for (int s = 0; s < 4; s++) {        // k16 steps
            int cb = s * 2;
            uint32_t af[2][4], bf[2][4];
#pragma unroll
            for (int mt = 0; mt < 2; mt++) {
                int r = wm * 32 + mt * 16 + la15;
                int c = cb + kadd;
                LDSM4(af[mt][0], af[mt][1], af[mt][2], af[mt][3],
                      cvta_s(&Ab[r * BK + ((c ^ (r & 7)) << 3)]));
            }
#pragma unroll
            for (int bt = 0; bt < 2; bt++) {
                int r = wn * 32 + bt * 16 + browq;
                int c = cb + kbdd;
                LDSM4(bf[bt][0], bf[bt][1], bf[bt][2], bf[bt][3],
                      cvta_s(&Bb[r * BK + ((c ^ (r & 7)) << 3)]));
            }
#pragma unroll
            for (int mt = 0; mt < 2; mt++)
#pragma unroll
                for (int bt = 0; bt < 2; bt++) {
                    MMA(acc[mt][bt * 2],     af[mt], bf[bt][0], bf[bt][1]);
                    MMA(acc[mt][bt * 2 + 1], af[mt], bf[bt][2], bf[bt][3]);
                }
        }
    }

    // fused loss: (pred/255 - int_sum/255)^2
    int gid = lane >> 2, tig = lane & 3;
    float lsum = 0.f;
#pragma unroll
    for (int mt = 0; mt < 2; mt++)
#pragma unroll
        for (int nt = 0; nt < 4; nt++) {
            int r  = m0 + wm * 32 + mt * 16 + gid;
            int nc = n0 + wn * 32 + nt * 8 + tig * 2;
            float e0 = fmaf(acc[mt][nt][0], 1.f / 255.f, -tval(ts, r,     nc));
            float e1 = fmaf(acc[mt][nt][1], 1.f / 255.f, -tval(ts, r,     nc + 1));
            float e2 = fmaf(acc[mt][nt][2], 1.f / 255.f, -tval(ts, r + 8, nc));
            float e3 = fmaf(acc[mt][nt][3], 1.f / 255.f, -tval(ts, r + 8, nc + 1));
            lsum += e0 * e0 + e1 * e1 + e2 * e2 + e3 * e3;
        }
#pragma unroll
    for (int o = 16; o > 0; o >>= 1)
        lsum += __shfl_xor_sync(0xffffffffu, lsum, o);
    if (lane == 0) s_red[wid] = lsum;
    __syncthreads();

    if (t == 0) {
        float s = 0.f;
#pragma unroll
        for (int i = 0; i < 8; i++) s += s_red[i];
        g_recon_part[blockIdx.y * (OUT_F / BN) + blockIdx.x] = s;
        __threadfence();
        int old = atomicAdd(&g_ticket, 1);
        s_last = (old == NCTA - 1) ? 1 : 0;
    }
    __syncthreads();

    if (s_last) {
        float rr = 0.f, ss = 0.f;
        for (int i = t; i < 3072; i += 256) rr += __ldcg(&g_reg_part[i]);
        if (t < NCTA) ss = __ldcg(&g_recon_part[t]);
#pragma unroll
        for (int o = 16; o > 0; o >>= 1) {
            rr += __shfl_xor_sync(0xffffffffu, rr, o);
            ss += __shfl_xor_sync(0xffffffffu, ss, o);
        }
        if ((t & 31) == 0) { s_red[t >> 5] = rr; s_red2[t >> 5] = ss; }
        __syncthreads();
        if (t == 0) {
            float R = 0.f, S = 0.f;
#pragma unroll
            for (int i = 0; i < 8; i++) { R += s_red[i]; S += s_red2[i]; }
            float recon = S * (1.0f / ((float)BATCH * OUT_F));
            float reg   = 0.001f * R * (1.0f / ((float)IN_F * (float)BITS));
            if (out_size > 0) out[0] = recon + reg;
            if (out_size > 1) out[1] = recon;
            if (out_size > 2) out[2] = reg;
            g_ticket = 0;   // reset for next graph replay
        }
    }
}

// ---------------- launch ----------------
extern "C" void kernel_launch(void* const* d_in, const int* in_sizes, int n_in,
                              void* d_out, int out_size) {
    const float* latent   = (const float*)d_in[0];
    const float* true_sum = (const float*)d_in[1];
    const float* weight   = (const float*)d_in[2];

    static int smem_set = 0;
    if (!smem_set) {
        cudaFuncSetAttribute(k_gemm_loss, cudaFuncAttributeMaxDynamicSharedMemorySize,
                             DSMEM_BYTES);
        smem_set = 1;
    }

    k_weights<<<dim3(IN_F / 32, OUT_F / 32), 256>>>(weight);
    k_convA<<<1024, 256>>>(latent);
    k_gemm_loss<<<dim3(OUT_F / BN, BATCH / BM), 256, DSMEM_BYTES>>>(
        true_sum, (float*)d_out, out_size);
}

// round 5
// speedup vs baseline: 1.1238x; 1.1238x over previous
#include <cuda_runtime.h>
#include <cuda_bf16.h>
#include <cstdint>

#define IN_F   4096
#define OUT_F  768
#define BITS   6144
#define BATCH  1024

#define BM 64
#define BN 64
#define BKK 64
#define NKC (IN_F / BKK)       // 64
#define NSTAGE 3
#define NCTA ((BATCH / BM) * (OUT_F / BN))   // 16*12 = 192
#define STG_ELEMS (BM * BKK)                 // 4096 uint16 per stage per operand
#define DSMEM_BYTES (NSTAGE * STG_ELEMS * 2 * 2)   // 49152

// ---------------- device scratch ----------------
__device__ __nv_bfloat16 g_wT[(size_t)OUT_F * IN_F];   // int_weights^T [768][4096]
__device__ __nv_bfloat16 g_lat[(size_t)BATCH * IN_F];  // latent bf16
__device__ float g_reg_part[3072];
__device__ float g_recon_part[NCTA];
__device__ int   g_ticket;

// ---------------- helpers ----------------
__device__ __forceinline__ float tanh_fast(float x) {
    float y; asm("tanh.approx.f32 %0, %1;" : "=f"(y) : "f"(x)); return y;
}
__device__ __forceinline__ uint32_t cvta_s(const void* p) {
    return (uint32_t)__cvta_generic_to_shared(p);
}
#define CP_ASYNC16(s, g) asm volatile("cp.async.cg.shared.global [%0], [%1], 16;\n" :: "r"(s), "l"(g))
#define CP_COMMIT        asm volatile("cp.async.commit_group;\n" ::: "memory")
#define CP_WAIT0         asm volatile("cp.async.wait_group 0;\n" ::: "memory")
#define CP_WAIT1         asm volatile("cp.async.wait_group 1;\n" ::: "memory")
#define LDSM4(r0, r1, r2, r3, a) \
    asm volatile("ldmatrix.sync.aligned.m8n8.x4.shared.b16 {%0,%1,%2,%3}, [%4];\n" \
                 : "=r"(r0), "=r"(r1), "=r"(r2), "=r"(r3) : "r"(a))
#define MMA(d, a, b0, b1) \
    asm volatile("mma.sync.aligned.m16n8k16.row.col.f32.bf16.bf16.f32 " \
                 "{%0,%1,%2,%3},{%4,%5,%6,%7},{%8,%9},{%0,%1,%2,%3};\n" \
                 : "+f"(d[0]), "+f"(d[1]), "+f"(d[2]), "+f"(d[3]) \
                 : "r"(a[0]), "r"(a[1]), "r"(a[2]), "r"(a[3]), "r"(b0), "r"(b1))

// ---------------- fused pre-pass: weights transform + latent convert ----------------
// blocks [0, 3072): sigmoid(weight) -> reg partials + int_weights^T bf16
// blocks [3072, 4096): latent fp32 -> bf16
__global__ void k_pre(const float* __restrict__ w, const float* __restrict__ lat) {
    int bx = blockIdx.x;
    int t = threadIdx.x;

    if (bx < 3072) {
        __shared__ float s_iw[32][33];
        __shared__ float s_red[8];
        const float pw[8] = {1.f, 2.f, 4.f, 8.f, 16.f, 32.f, 64.f, -128.f};

        int k0 = (bx & 127) * 32;
        int n0 = (bx >> 7) * 32;

        float regloc = 0.f;
#pragma unroll
        for (int i = 0; i < 4; i++) {
            int c = t + i * 256;
            int kk = c >> 5, nn = c & 31;
            const float4* p = reinterpret_cast<const float4*>(
                w + (size_t)(k0 + kk) * BITS + (size_t)(n0 + nn) * 8);
            float4 w0 = p[0], w1 = p[1];
            float xs[8] = {w0.x, w0.y, w0.z, w0.w, w1.x, w1.y, w1.z, w1.w};
            float iw = 0.f;
#pragma unroll
            for (int b = 0; b < 8; b++) {
                float th = tanh_fast(0.5f * xs[b]);      // sigmoid = 0.5 + 0.5*th
                iw = fmaf(0.5f + 0.5f * th, pw[b], iw);
                regloc += 0.5f - 0.5f * fabsf(th);       // min(p, 1-p)
            }
            s_iw[kk][nn] = iw;
        }
        __syncthreads();
#pragma unroll
        for (int i = 0; i < 4; i++) {
            int c = t + i * 256;
            int nn = c >> 5, kk = c & 31;
            g_wT[(size_t)(n0 + nn) * IN_F + (k0 + kk)] = __float2bfloat16(s_iw[kk][nn]);
        }
#pragma unroll
        for (int o = 16; o > 0; o >>= 1)
            regloc += __shfl_xor_sync(0xffffffffu, regloc, o);
        if ((t & 31) == 0) s_red[t >> 5] = regloc;
        __syncthreads();
        if (t == 0) {
            float s = 0.f;
#pragma unroll
            for (int i = 0; i < 8; i++) s += s_red[i];
            g_reg_part[bx] = s;
        }
    } else {
        int i = (bx - 3072) * 256 + t;
        const int stride = 1024 * 256;   // 262144 float4 slots, 1M total
        const float4* src = reinterpret_cast<const float4*>(lat);
        __nv_bfloat162* o = reinterpret_cast<__nv_bfloat162*>(g_lat);
        float4 v[4];
#pragma unroll
        for (int j = 0; j < 4; j++) v[j] = src[i + j * stride];
#pragma unroll
        for (int j = 0; j < 4; j++) {
            int idx = i + j * stride;
            o[2 * idx]     = __floats2bfloat162_rn(v[j].x, v[j].y);
            o[2 * idx + 1] = __floats2bfloat162_rn(v[j].z, v[j].w);
        }
    }
}

// int_sum(r,n)/255 on the fly from true_sum
__device__ __forceinline__ float tval(const float* __restrict__ ts, int r, int n) {
    const float4* p = reinterpret_cast<const float4*>(ts + ((size_t)r * OUT_F + n) * 8);
    float4 a = p[0], b = p[1];
    return (a.x + 2.f * a.y + 4.f * a.z + 8.f * a.w
            + 16.f * b.x + 32.f * b.y + 64.f * b.z - 128.f * b.w) * (1.0f / 255.0f);
}

// stage loader: per thread 2 A-chunks + 2 B-chunks of 16B (rows row0, row0+32)
__device__ __forceinline__ void load_tile(
    uint16_t* Asb, uint16_t* Bsb,
    const __nv_bfloat16* gA, const __nv_bfloat16* gB,
    int kbase, int row0, int chunk0)
{
    int sw = (chunk0 ^ (row0 & 7)) << 3;            // same for row0 and row0+32
    CP_ASYNC16(cvta_s(&Asb[row0 * BKK + sw]),
               gA + (size_t)row0 * IN_F + kbase + chunk0 * 8);
    CP_ASYNC16(cvta_s(&Asb[(row0 + 32) * BKK + sw]),
               gA + (size_t)(row0 + 32) * IN_F + kbase + chunk0 * 8);
    CP_ASYNC16(cvta_s(&Bsb[row0 * BKK + sw]),
               gB + (size_t)row0 * IN_F + kbase + chunk0 * 8);
    CP_ASYNC16(cvta_s(&Bsb[(row0 + 32) * BKK + sw]),
               gB + (size_t)(row0 + 32) * IN_F + kbase + chunk0 * 8);
}

// GEMM (ldmatrix + mma.sync, 3-stage single-sync pipeline) + fused loss + last-CTA reduce
__global__ void __launch_bounds__(256, 2)
k_gemm_loss(const float* __restrict__ ts, float* __restrict__ out, int out_size) {
    extern __shared__ __align__(16) uint8_t dsm[];
    uint16_t* As = (uint16_t*)dsm;                     // NSTAGE * 64*64
    uint16_t* Bs = As + NSTAGE * STG_ELEMS;            // NSTAGE * 64*64

    __shared__ float s_red[8], s_red2[8];
    __shared__ int s_last;

    int n0 = blockIdx.x * BN;   // 12
    int m0 = blockIdx.y * BM;   // 16
    int t = threadIdx.x;
    int wid = t >> 5, lane = t & 31;
    int wm = wid & 1, wn = wid >> 1;

    int row0 = t >> 3, chunk0 = t & 7;

    const __nv_bfloat16* gA = g_lat + (size_t)m0 * IN_F;
    const __nv_bfloat16* gB = g_wT + (size_t)n0 * IN_F;

    float acc[2][2][4] = {};

    int rA0 = wm * 32 + (lane & 15);
    int rA1 = rA0 + 16;
    int kA  = lane >> 4;
    int rB  = wn * 16 + ((lane >> 4) << 3) + (lane & 7);
    int kB  = (lane >> 3) & 1;

    // prologue: stages 0,1
    load_tile(As, Bs, gA, gB, 0, row0, chunk0); CP_COMMIT;
    load_tile(As + STG_ELEMS, Bs + STG_ELEMS, gA, gB, BKK, row0, chunk0); CP_COMMIT;

    int buf = 0;
    for (int kc = 0; kc < NKC; kc++) {
        if (kc + 1 < NKC) { CP_WAIT1; } else { CP_WAIT0; }
        __syncthreads();

        if (kc + 2 < NKC) {
            int b2 = buf + 2; if (b2 >= NSTAGE) b2 -= NSTAGE;
            load_tile(As + b2 * STG_ELEMS, Bs + b2 * STG_ELEMS,
                      gA, gB, (kc + 2) * BKK, row0, chunk0);
            CP_COMMIT;
        }

        const uint16_t* Ab = As + buf * STG_ELEMS;
        const uint16_t* Bb = Bs + buf * STG_ELEMS;
#pragma unroll
        for (int kc8 = 0; kc8 < 8; kc8 += 2) {
            uint32_t a0[4], a1[4], b[4];
            int ka = kc8 + kA;
            int kb = kc8 + kB;
            LDSM4(a0[0], a0[1], a0[2], a0[3],
                  cvta_s(&Ab[rA0 * BKK + ((ka ^ (rA0 & 7)) << 3)]));
            LDSM4(a1[0], a1[1], a1[2], a1[3],
                  cvta_s(&Ab[rA1 * BKK + ((ka ^ (rA1 & 7)) << 3)]));
            LDSM4(b[0], b[1], b[2], b[3],
                  cvta_s(&Bb[rB * BKK + ((kb ^ (rB & 7)) << 3)]));
            MMA(acc[0][0], a0, b[0], b[1]);
            MMA(acc[0][1], a0, b[2], b[3]);
            MMA(acc[1][0], a1, b[0], b[1]);
            MMA(acc[1][1], a1, b[2], b[3]);
        }
        buf++; if (buf >= NSTAGE) buf = 0;
    }

    // fused loss: (pred/255 - int_sum/255)^2
    int gid = lane >> 2, tig = lane & 3;
    float lsum = 0.f;
#pragma unroll
    for (int mt = 0; mt < 2; mt++)
#pragma unroll
        for (int nt = 0; nt < 2; nt++) {
            int r  = m0 + wm * 32 + mt * 16 + gid;
            int nc = n0 + wn * 16 + nt * 8 + tig * 2;
            float e0 = fmaf(acc[mt][nt][0], 1.f / 255.f, -tval(ts, r,     nc));
            float e1 = fmaf(acc[mt][nt][1], 1.f / 255.f, -tval(ts, r,     nc + 1));
            float e2 = fmaf(acc[mt][nt][2], 1.f / 255.f, -tval(ts, r + 8, nc));
            float e3 = fmaf(acc[mt][nt][3], 1.f / 255.f, -tval(ts, r + 8, nc + 1));
            lsum += e0 * e0 + e1 * e1 + e2 * e2 + e3 * e3;
        }
#pragma unroll
    for (int o = 16; o > 0; o >>= 1)
        lsum += __shfl_xor_sync(0xffffffffu, lsum, o);
    if (lane == 0) s_red[wid] = lsum;
    __syncthreads();

    if (t == 0) {
        float s = 0.f;
#pragma unroll
        for (int i = 0; i < 8; i++) s += s_red[i];
        g_recon_part[blockIdx.y * (OUT_F / BN) + blockIdx.x] = s;
        __threadfence();
        int old = atomicAdd(&g_ticket, 1);
        s_last = (old == NCTA - 1) ? 1 : 0;
    }
    __syncthreads();

    if (s_last) {
        float rr = 0.f, ss = 0.f;
        for (int i = t; i < 3072; i += 256) rr += __ldcg(&g_reg_part[i]);
        if (t < NCTA) ss = __ldcg(&g_recon_part[t]);
#pragma unroll
        for (int o = 16; o > 0; o >>= 1) {
            rr += __shfl_xor_sync(0xffffffffu, rr, o);
            ss += __shfl_xor_sync(0xffffffffu, ss, o);
        }
        if ((t & 31) == 0) { s_red[t >> 5] = rr; s_red2[t >> 5] = ss; }
        __syncthreads();
        if (t == 0) {
            float R = 0.f, S = 0.f;
#pragma unroll
            for (int i = 0; i < 8; i++) { R += s_red[i]; S += s_red2[i]; }
            float recon = S * (1.0f / ((float)BATCH * OUT_F));
            float reg   = 0.001f * R * (1.0f / ((float)IN_F * (float)BITS));
            if (out_size > 0) out[0] = recon + reg;
            if (out_size > 1) out[1] = recon;
            if (out_size > 2) out[2] = reg;
            g_ticket = 0;   // reset for next graph replay
        }
    }
}

// ---------------- launch ----------------
extern "C" void kernel_launch(void* const* d_in, const int* in_sizes, int n_in,
                              void* d_out, int out_size) {
    const float* latent   = (const float*)d_in[0];
    const float* true_sum = (const float*)d_in[1];
    const float* weight   = (const float*)d_in[2];

    static int smem_set = 0;
    if (!smem_set) {
        cudaFuncSetAttribute(k_gemm_loss, cudaFuncAttributeMaxDynamicSharedMemorySize,
                             DSMEM_BYTES);
        smem_set = 1;
    }

    k_pre<<<4096, 256>>>(weight, latent);
    k_gemm_loss<<<dim3(OUT_F / BN, BATCH / BM), 256, DSMEM_BYTES>>>(
        true_sum, (float*)d_out, out_size);
}

// round 6
// speedup vs baseline: 1.2399x; 1.1033x over previous
#include <cuda_runtime.h>
#include <cuda_bf16.h>
#include <cstdint>

#define IN_F   4096
#define OUT_F  768
#define BITS   6144
#define BATCH  1024

#define BM 64
#define BN 96
#define BKK 64
#define NKC (IN_F / BKK)       // 64
#define NSTAGE 4
#define GX (OUT_F / BN)        // 8
#define GY (BATCH / BM)        // 16
#define NCTA (GX * GY)         // 128
#define A_ST (BM * BKK)        // 4096 u16 = 8KB
#define B_ST (BN * BKK)        // 6144 u16 = 12KB
#define DSMEM_BYTES (NSTAGE * (A_ST + B_ST) * 2)   // 80KB

// ---------------- device scratch ----------------
__device__ __nv_bfloat16 g_wT[(size_t)OUT_F * IN_F];
__device__ __nv_bfloat16 g_lat[(size_t)BATCH * IN_F];
__device__ float g_reg_part[3072];
__device__ float g_recon_part[NCTA];
__device__ int   g_ticket;

// ---------------- helpers ----------------
__device__ __forceinline__ float tanh_fast(float x) {
    float y; asm("tanh.approx.f32 %0, %1;" : "=f"(y) : "f"(x)); return y;
}
__device__ __forceinline__ uint32_t cvta_s(const void* p) {
    return (uint32_t)__cvta_generic_to_shared(p);
}
#define CP_ASYNC16(s, g) asm volatile("cp.async.cg.shared.global [%0], [%1], 16;\n" :: "r"(s), "l"(g))
#define CP_COMMIT        asm volatile("cp.async.commit_group;\n" ::: "memory")
#define CP_WAIT0         asm volatile("cp.async.wait_group 0;\n" ::: "memory")
#define CP_WAIT1         asm volatile("cp.async.wait_group 1;\n" ::: "memory")
#define CP_WAIT2         asm volatile("cp.async.wait_group 2;\n" ::: "memory")
#define LDSM4(r0, r1, r2, r3, a) \
    asm volatile("ldmatrix.sync.aligned.m8n8.x4.shared.b16 {%0,%1,%2,%3}, [%4];\n" \
                 : "=r"(r0), "=r"(r1), "=r"(r2), "=r"(r3) : "r"(a))
#define MMA(d, a, b0, b1) \
    asm volatile("mma.sync.aligned.m16n8k16.row.col.f32.bf16.bf16.f32 " \
                 "{%0,%1,%2,%3},{%4,%5,%6,%7},{%8,%9},{%0,%1,%2,%3};\n" \
                 : "+f"(d[0]), "+f"(d[1]), "+f"(d[2]), "+f"(d[3]) \
                 : "r"(a[0]), "r"(a[1]), "r"(a[2]), "r"(a[3]), "r"(b0), "r"(b1))

// ---------------- fused pre-pass ----------------
// blocks [0,3072): sigmoid(weight) -> reg partials + int_weights^T bf16
// blocks [3072,4096): latent fp32 -> bf16
__global__ void k_pre(const float* __restrict__ w, const float* __restrict__ lat) {
    int bx = blockIdx.x;
    int t = threadIdx.x;

    if (bx < 3072) {
        __shared__ float s_iw[32][33];
        __shared__ float s_red[8];
        // pw/2 with sign bit folded: iw = sum(pw_b * sigmoid) = -0.5 + sum((pw_b/2)*tanh(x/2))
        const float pwh[8] = {0.5f, 1.f, 2.f, 4.f, 8.f, 16.f, 32.f, -64.f};

        int k0 = (bx & 127) * 32;
        int n0 = (bx >> 7) * 32;

        float regloc = 0.f;
#pragma unroll
        for (int i = 0; i < 4; i++) {
            int c = t + i * 256;
            int kk = c >> 5, nn = c & 31;
            const float4* p = reinterpret_cast<const float4*>(
                w + (size_t)(k0 + kk) * BITS + (size_t)(n0 + nn) * 8);
            float4 w0 = p[0], w1 = p[1];
            float xs[8] = {w0.x, w0.y, w0.z, w0.w, w1.x, w1.y, w1.z, w1.w};
            float iwt = 0.f, sab = 0.f;
#pragma unroll
            for (int b = 0; b < 8; b++) {
                float th = tanh_fast(0.5f * xs[b]);
                iwt = fmaf(th, pwh[b], iwt);
                sab += fabsf(th);
            }
            s_iw[kk][nn] = iwt - 0.5f;
            regloc += fmaf(-0.5f, sab, 4.0f);   // sum of min(p,1-p) over 8 bits
        }
        __syncthreads();
#pragma unroll
        for (int i = 0; i < 4; i++) {
            int c = t + i * 256;
            int nn = c >> 5, kk = c & 31;
            g_wT[(size_t)(n0 + nn) * IN_F + (k0 + kk)] = __float2bfloat16(s_iw[kk][nn]);
        }
#pragma unroll
        for (int o = 16; o > 0; o >>= 1)
            regloc += __shfl_xor_sync(0xffffffffu, regloc, o);
        if ((t & 31) == 0) s_red[t >> 5] = regloc;
        __syncthreads();
        if (t == 0) {
            float s = 0.f;
#pragma unroll
            for (int i = 0; i < 8; i++) s += s_red[i];
            g_reg_part[bx] = s;
        }
    } else {
        int i = (bx - 3072) * 256 + t;
        const int stride = 1024 * 256;
        const float4* src = reinterpret_cast<const float4*>(lat);
        __nv_bfloat162* o = reinterpret_cast<__nv_bfloat162*>(g_lat);
        float4 v[4];
#pragma unroll
        for (int j = 0; j < 4; j++) v[j] = src[i + j * stride];
#pragma unroll
        for (int j = 0; j < 4; j++) {
            int idx = i + j * stride;
            o[2 * idx]     = __floats2bfloat162_rn(v[j].x, v[j].y);
            o[2 * idx + 1] = __floats2bfloat162_rn(v[j].z, v[j].w);
        }
    }
}

// int_sum(r,n)/255 from true_sum
__device__ __forceinline__ float tval(const float* __restrict__ ts, int r, int n) {
    const float4* p = reinterpret_cast<const float4*>(ts + ((size_t)r * OUT_F + n) * 8);
    float4 a = p[0], b = p[1];
    return (a.x + 2.f * a.y + 4.f * a.z + 8.f * a.w
            + 16.f * b.x + 32.f * b.y + 64.f * b.z - 128.f * b.w) * (1.0f / 255.0f);
}

// stage loader: A 2x16B (rows t>>2), B 3x16B
__device__ __forceinline__ void load_tile(
    uint16_t* Asb, uint16_t* Bsb,
    const __nv_bfloat16* gA, const __nv_bfloat16* gB, int kbase, int t)
{
    {   // A: 512 vectors, 2 per thread
        int rowa = t >> 2, cb = (t & 3) * 2;
#pragma unroll
        for (int j = 0; j < 2; j++) {
            int c = cb + j;
            int sw = (c ^ (rowa & 7)) << 3;
            CP_ASYNC16(cvta_s(&Asb[rowa * BKK + sw]),
                       gA + (size_t)rowa * IN_F + kbase + c * 8);
        }
    }
    {   // B: 768 vectors, 3 per thread
#pragma unroll
        for (int j = 0; j < 3; j++) {
            int id = t + j * 256;
            int rowb = id >> 3, c = id & 7;
            int sw = (c ^ (rowb & 7)) << 3;
            CP_ASYNC16(cvta_s(&Bsb[rowb * BKK + sw]),
                       gB + (size_t)rowb * IN_F + kbase + c * 8);
        }
    }
}

// GEMM 64x96 tiles, 128 CTAs (single wave), 4-stage cp.async, fused loss + last-CTA reduce
__global__ void __launch_bounds__(256)
k_gemm_loss(const float* __restrict__ ts, float* __restrict__ out, int out_size) {
    extern __shared__ __align__(16) uint8_t dsm[];
    uint16_t* As = (uint16_t*)dsm;             // NSTAGE * A_ST
    uint16_t* Bs = As + NSTAGE * A_ST;         // NSTAGE * B_ST

    __shared__ float s_red[8], s_red2[8];
    __shared__ int s_last;

    int n0 = blockIdx.x * BN;   // 8
    int m0 = blockIdx.y * BM;   // 16
    int t = threadIdx.x;
    int wid = t >> 5, lane = t & 31;
    int wm = wid & 3, wn = wid >> 2;           // 4 M-warps x 2 N-warps (16x48)

    const __nv_bfloat16* gA = g_lat + (size_t)m0 * IN_F;
    const __nv_bfloat16* gB = g_wT + (size_t)n0 * IN_F;

    float acc[6][4] = {};   // n-sub j*8, j=0..5

    // ldmatrix lane addressing
    int rA = wm * 16 + (lane & 15);            // A row
    int kA = lane >> 4;                        // +0/+1 k-chunk
    int rBq = ((lane >> 4) << 3) + (lane & 7); // B row within 16-block
    int kB = (lane >> 3) & 1;

    // prologue: stages 0..2
    load_tile(As, Bs, gA, gB, 0, t); CP_COMMIT;
    load_tile(As + A_ST, Bs + B_ST, gA, gB, BKK, t); CP_COMMIT;
    load_tile(As + 2 * A_ST, Bs + 2 * B_ST, gA, gB, 2 * BKK, t); CP_COMMIT;

    int buf = 0;
    for (int kc = 0; kc < NKC; kc++) {
        if (kc < NKC - 2)       { CP_WAIT2; }
        else if (kc == NKC - 2) { CP_WAIT1; }
        else                    { CP_WAIT0; }
        __syncthreads();

        if (kc + 3 < NKC) {
            int b3 = buf + 3; if (b3 >= NSTAGE) b3 -= NSTAGE;
            load_tile(As + b3 * A_ST, Bs + b3 * B_ST, gA, gB, (kc + 3) * BKK, t);
            CP_COMMIT;
        }

        const uint16_t* Ab = As + buf * A_ST;
        const uint16_t* Bb = Bs + buf * B_ST;
#pragma unroll
        for (int s = 0; s < 4; s++) {
            int cb = s * 2;
            uint32_t af[4], bf[3][4];
            {
                int c = cb + kA;
                LDSM4(af[0], af[1], af[2], af[3],
                      cvta_s(&Ab[rA * BKK + ((c ^ (rA & 7)) << 3)]));
            }
#pragma unroll
            for (int j = 0; j < 3; j++) {
                int r = wn * 48 + j * 16 + rBq;
                int c = cb + kB;
                LDSM4(bf[j][0], bf[j][1], bf[j][2], bf[j][3],
                      cvta_s(&Bb[r * BKK + ((c ^ (r & 7)) << 3)]));
            }
#pragma unroll
            for (int j = 0; j < 3; j++) {
                MMA(acc[2 * j],     af, bf[j][0], bf[j][1]);
                MMA(acc[2 * j + 1], af, bf[j][2], bf[j][3]);
            }
        }
        buf++; if (buf >= NSTAGE) buf = 0;
    }

    // fused loss
    int gid = lane >> 2, tig = lane & 3;
    float lsum = 0.f;
#pragma unroll
    for (int j = 0; j < 6; j++) {
        int r  = m0 + wm * 16 + gid;
        int nc = n0 + wn * 48 + (j >> 1) * 16 + (j & 1) * 8 + tig * 2;
        float e0 = fmaf(acc[j][0], 1.f / 255.f, -tval(ts, r,     nc));
        float e1 = fmaf(acc[j][1], 1.f / 255.f, -tval(ts, r,     nc + 1));
        float e2 = fmaf(acc[j][2], 1.f / 255.f, -tval(ts, r + 8, nc));
        float e3 = fmaf(acc[j][3], 1.f / 255.f, -tval(ts, r + 8, nc + 1));
        lsum += e0 * e0 + e1 * e1 + e2 * e2 + e3 * e3;
    }
#pragma unroll
    for (int o = 16; o > 0; o >>= 1)
        lsum += __shfl_xor_sync(0xffffffffu, lsum, o);
    if (lane == 0) s_red[wid] = lsum;
    __syncthreads();

    if (t == 0) {
        float s = 0.f;
#pragma unroll
        for (int i = 0; i < 8; i++) s += s_red[i];
        g_recon_part[blockIdx.y * GX + blockIdx.x] = s;
        __threadfence();
        int old = atomicAdd(&g_ticket, 1);
        s_last = (old == NCTA - 1) ? 1 : 0;
    }
    __syncthreads();

    if (s_last) {
        float rr = 0.f, ss = 0.f;
        for (int i = t; i < 3072; i += 256) rr += __ldcg(&g_reg_part[i]);
        if (t < NCTA) ss = __ldcg(&g_recon_part[t]);
#pragma unroll
        for (int o = 16; o > 0; o >>= 1) {
            rr += __shfl_xor_sync(0xffffffffu, rr, o);
            ss += __shfl_xor_sync(0xffffffffu, ss, o);
        }
        if ((t & 31) == 0) { s_red[t >> 5] = rr; s_red2[t >> 5] = ss; }
        __syncthreads();
        if (t == 0) {
            float R = 0.f, S = 0.f;
#pragma unroll
            for (int i = 0; i < 8; i++) { R += s_red[i]; S += s_red2[i]; }
            float recon = S * (1.0f / ((float)BATCH * OUT_F));
            float reg   = 0.001f * R * (1.0f / ((float)IN_F * (float)BITS));
            if (out_size > 0) out[0] = recon + reg;
            if (out_size > 1) out[1] = recon;
            if (out_size > 2) out[2] = reg;
            g_ticket = 0;
        }
    }
}

// ---------------- launch ----------------
extern "C" void kernel_launch(void* const* d_in, const int* in_sizes, int n_in,
                              void* d_out, int out_size) {
    const float* latent   = (const float*)d_in[0];
    const float* true_sum = (const float*)d_in[1];
    const float* weight   = (const float*)d_in[2];

    static int smem_set = 0;
    if (!smem_set) {
        cudaFuncSetAttribute(k_gemm_loss, cudaFuncAttributeMaxDynamicSharedMemorySize,
                             DSMEM_BYTES);
        smem_set = 1;
    }

    k_pre<<<4096, 256>>>(weight, latent);
    k_gemm_loss<<<dim3(GX, GY), 256, DSMEM_BYTES>>>(true_sum, (float*)d_out, out_size);
}

// round 7
// speedup vs baseline: 1.2987x; 1.0474x over previous
#include <cuda_runtime.h>
#include <cuda_bf16.h>
#include <cstdint>

#define IN_F   4096
#define OUT_F  768
#define BITS   6144
#define BATCH  1024

#define BM 64
#define BN 96
#define BKK 128
#define NKC (IN_F / BKK)       // 32
#define NSTAGE 3
#define GX (OUT_F / BN)        // 8
#define GY (BATCH / BM)        // 16
#define NCTA (GX * GY)         // 128
#define A_ST (BM * BKK)        // 8192 u16 = 16KB
#define B_ST (BN * BKK)        // 12288 u16 = 24KB
#define DSMEM_BYTES (NSTAGE * (A_ST + B_ST) * 2)   // 122880

// ---------------- device scratch ----------------
__device__ __nv_bfloat16 g_wT[(size_t)OUT_F * IN_F];
__device__ __nv_bfloat16 g_lat[(size_t)BATCH * IN_F];
__device__ float g_reg_part[3072];
__device__ float g_recon_part[NCTA];
__device__ int   g_ticket;

// ---------------- helpers ----------------
__device__ __forceinline__ float tanh_fast(float x) {
    float y; asm("tanh.approx.f32 %0, %1;" : "=f"(y) : "f"(x)); return y;
}
__device__ __forceinline__ uint32_t cvta_s(const void* p) {
    return (uint32_t)__cvta_generic_to_shared(p);
}
#define CP_ASYNC16(s, g) asm volatile("cp.async.cg.shared.global [%0], [%1], 16;\n" :: "r"(s), "l"(g))
#define CP_COMMIT        asm volatile("cp.async.commit_group;\n" ::: "memory")
#define CP_WAIT0         asm volatile("cp.async.wait_group 0;\n" ::: "memory")
#define CP_WAIT1         asm volatile("cp.async.wait_group 1;\n" ::: "memory")
#define LDSM4(r0, r1, r2, r3, a) \
    asm volatile("ldmatrix.sync.aligned.m8n8.x4.shared.b16 {%0,%1,%2,%3}, [%4];\n" \
                 : "=r"(r0), "=r"(r1), "=r"(r2), "=r"(r3) : "r"(a))
#define MMA(d, a, b0, b1) \
    asm volatile("mma.sync.aligned.m16n8k16.row.col.f32.bf16.bf16.f32 " \
                 "{%0,%1,%2,%3},{%4,%5,%6,%7},{%8,%9},{%0,%1,%2,%3};\n" \
                 : "+f"(d[0]), "+f"(d[1]), "+f"(d[2]), "+f"(d[3]) \
                 : "r"(a[0]), "r"(a[1]), "r"(a[2]), "r"(a[3]), "r"(b0), "r"(b1))

// swizzled elem offset for 256B rows: unit = (c&8) | ((c&7)^(r&7))
__device__ __forceinline__ int swz(int row, int c) {
    return row * BKK + (((c & 8) | ((c & 7) ^ (row & 7))) << 3);
}

// ---------------- fused pre-pass ----------------
__global__ void k_pre(const float* __restrict__ w, const float* __restrict__ lat) {
    int bx = blockIdx.x;
    int t = threadIdx.x;

    if (bx < 3072) {
        __shared__ float s_iw[32][33];
        __shared__ float s_red[8];
        const float pwh[8] = {0.5f, 1.f, 2.f, 4.f, 8.f, 16.f, 32.f, -64.f};

        int k0 = (bx & 127) * 32;
        int n0 = (bx >> 7) * 32;

        float regloc = 0.f;
#pragma unroll
        for (int i = 0; i < 4; i++) {
            int c = t + i * 256;
            int kk = c >> 5, nn = c & 31;
            const float4* p = reinterpret_cast<const float4*>(
                w + (size_t)(k0 + kk) * BITS + (size_t)(n0 + nn) * 8);
            float4 w0 = p[0], w1 = p[1];
            float xs[8] = {w0.x, w0.y, w0.z, w0.w, w1.x, w1.y, w1.z, w1.w};
            float iwt = 0.f, sab = 0.f;
#pragma unroll
            for (int b = 0; b < 8; b++) {
                float th = tanh_fast(0.5f * xs[b]);
                iwt = fmaf(th, pwh[b], iwt);
                sab += fabsf(th);
            }
            s_iw[kk][nn] = iwt - 0.5f;
            regloc += fmaf(-0.5f, sab, 4.0f);
        }
        __syncthreads();
#pragma unroll
        for (int i = 0; i < 4; i++) {
            int c = t + i * 256;
            int nn = c >> 5, kk = c & 31;
            g_wT[(size_t)(n0 + nn) * IN_F + (k0 + kk)] = __float2bfloat16(s_iw[kk][nn]);
        }
#pragma unroll
        for (int o = 16; o > 0; o >>= 1)
            regloc += __shfl_xor_sync(0xffffffffu, regloc, o);
        if ((t & 31) == 0) s_red[t >> 5] = regloc;
        __syncthreads();
        if (t == 0) {
            float s = 0.f;
#pragma unroll
            for (int i = 0; i < 8; i++) s += s_red[i];
            g_reg_part[bx] = s;
        }
    } else {
        int i = (bx - 3072) * 256 + t;
        const int stride = 1024 * 256;
        const float4* src = reinterpret_cast<const float4*>(lat);
        __nv_bfloat162* o = reinterpret_cast<__nv_bfloat162*>(g_lat);
        float4 v[4];
#pragma unroll
        for (int j = 0; j < 4; j++) v[j] = src[i + j * stride];
#pragma unroll
        for (int j = 0; j < 4; j++) {
            int idx = i + j * stride;
            o[2 * idx]     = __floats2bfloat162_rn(v[j].x, v[j].y);
            o[2 * idx + 1] = __floats2bfloat162_rn(v[j].z, v[j].w);
        }
    }
}

// int_sum(r,n)/255 from true_sum
__device__ __forceinline__ float tval(const float* __restrict__ ts, int r, int n) {
    const float4* p = reinterpret_cast<const float4*>(ts + ((size_t)r * OUT_F + n) * 8);
    float4 a = p[0], b = p[1];
    return (a.x + 2.f * a.y + 4.f * a.z + 8.f * a.w
            + 16.f * b.x + 32.f * b.y + 64.f * b.z - 128.f * b.w) * (1.0f / 255.0f);
}

// stage loader: A 4x16B, B 6x16B per thread (BKK=128: 16 chunks/row)
__device__ __forceinline__ void load_tile(
    uint16_t* Asb, uint16_t* Bsb,
    const __nv_bfloat16* gA, const __nv_bfloat16* gB, int kbase, int t)
{
#pragma unroll
    for (int j = 0; j < 4; j++) {
        int id = t + j * 256;
        int row = id >> 4, c = id & 15;
        CP_ASYNC16(cvta_s(&Asb[swz(row, c)]),
                   gA + (size_t)row * IN_F + kbase + c * 8);
    }
#pragma unroll
    for (int j = 0; j < 6; j++) {
        int id = t + j * 256;
        int row = id >> 4, c = id & 15;
        CP_ASYNC16(cvta_s(&Bsb[swz(row, c)]),
                   gB + (size_t)row * IN_F + kbase + c * 8);
    }
}

// GEMM 64x96 tiles, 128 CTAs, BKK=128, manual fragment double-buffer
__global__ void __launch_bounds__(256, 1)
k_gemm_loss(const float* __restrict__ ts, float* __restrict__ out, int out_size) {
    extern __shared__ __align__(16) uint8_t dsm[];
    uint16_t* As = (uint16_t*)dsm;             // NSTAGE * A_ST
    uint16_t* Bs = As + NSTAGE * A_ST;         // NSTAGE * B_ST

    __shared__ float s_red[8], s_red2[8];
    __shared__ int s_last;

    int n0 = blockIdx.x * BN;
    int m0 = blockIdx.y * BM;
    int t = threadIdx.x;
    int wid = t >> 5, lane = t & 31;
    int wm = wid & 3, wn = wid >> 2;           // warp tile 16x48

    const __nv_bfloat16* gA = g_lat + (size_t)m0 * IN_F;
    const __nv_bfloat16* gB = g_wT + (size_t)n0 * IN_F;

    float acc[6][4] = {};

    int rA = wm * 16 + (lane & 15);
    int kA = lane >> 4;
    int rB0 = wn * 48 + ((lane >> 4) << 3) + (lane & 7);
    int kB = (lane >> 3) & 1;

    // prologue: stages 0,1
    load_tile(As, Bs, gA, gB, 0, t); CP_COMMIT;
    load_tile(As + A_ST, Bs + B_ST, gA, gB, BKK, t); CP_COMMIT;

    uint32_t af[2][4], bf[2][3][4];

    int buf = 0;
    for (int kc = 0; kc < NKC; kc++) {
        if (kc + 1 < NKC) { CP_WAIT1; } else { CP_WAIT0; }
        __syncthreads();

        if (kc + 2 < NKC) {
            int b2 = buf + 2; if (b2 >= NSTAGE) b2 -= NSTAGE;
            load_tile(As + b2 * A_ST, Bs + b2 * B_ST, gA, gB, (kc + 2) * BKK, t);
            CP_COMMIT;
        }

        const uint16_t* Ab = As + buf * A_ST;
        const uint16_t* Bb = Bs + buf * B_ST;

        // preload step-0 fragments
        {
            int c = kA;
            LDSM4(af[0][0], af[0][1], af[0][2], af[0][3], cvta_s(&Ab[swz(rA, c)]));
            int c2 = kB;
#pragma unroll
            for (int j = 0; j < 3; j++)
                LDSM4(bf[0][j][0], bf[0][j][1], bf[0][j][2], bf[0][j][3],
                      cvta_s(&Bb[swz(rB0 + j * 16, c2)]));
        }
#pragma unroll
        for (int s = 0; s < 8; s++) {        // 8 k16 steps
            int w = s & 1;
            if (s < 7) {
                int c = 2 * (s + 1) + kA;
                LDSM4(af[w ^ 1][0], af[w ^ 1][1], af[w ^ 1][2], af[w ^ 1][3],
                      cvta_s(&Ab[swz(rA, c)]));
                int c2 = 2 * (s + 1) + kB;
#pragma unroll
                for (int j = 0; j < 3; j++)
                    LDSM4(bf[w ^ 1][j][0], bf[w ^ 1][j][1], bf[w ^ 1][j][2], bf[w ^ 1][j][3],
                          cvta_s(&Bb[swz(rB0 + j * 16, c2)]));
            }
#pragma unroll
            for (int j = 0; j < 3; j++) {
                MMA(acc[2 * j],     af[w], bf[w][j][0], bf[w][j][1]);
                MMA(acc[2 * j + 1], af[w], bf[w][j][2], bf[w][j][3]);
            }
        }
        buf++; if (buf >= NSTAGE) buf = 0;
    }

    // fused loss
    int gid = lane >> 2, tig = lane & 3;
    float lsum = 0.f;
#pragma unroll
    for (int j = 0; j < 6; j++) {
        int r  = m0 + wm * 16 + gid;
        int nc = n0 + wn * 48 + (j >> 1) * 16 + (j & 1) * 8 + tig * 2;
        float e0 = fmaf(acc[j][0], 1.f / 255.f, -tval(ts, r,     nc));
        float e1 = fmaf(acc[j][1], 1.f / 255.f, -tval(ts, r,     nc + 1));
        float e2 = fmaf(acc[j][2], 1.f / 255.f, -tval(ts, r + 8, nc));
        float e3 = fmaf(acc[j][3], 1.f / 255.f, -tval(ts, r + 8, nc + 1));
        lsum += e0 * e0 + e1 * e1 + e2 * e2 + e3 * e3;
    }
#pragma unroll
    for (int o = 16; o > 0; o >>= 1)
        lsum += __shfl_xor_sync(0xffffffffu, lsum, o);
    if (lane == 0) s_red[wid] = lsum;
    __syncthreads();

    if (t == 0) {
        float s = 0.f;
#pragma unroll
        for (int i = 0; i < 8; i++) s += s_red[i];
        g_recon_part[blockIdx.y * GX + blockIdx.x] = s;
        __threadfence();
        int old = atomicAdd(&g_ticket, 1);
        s_last = (old == NCTA - 1) ? 1 : 0;
    }
    __syncthreads();

    if (s_last) {
        float rr = 0.f, ss = 0.f;
        for (int i = t; i < 3072; i += 256) rr += __ldcg(&g_reg_part[i]);
        if (t < NCTA) ss = __ldcg(&g_recon_part[t]);
#pragma unroll
        for (int o = 16; o > 0; o >>= 1) {
            rr += __shfl_xor_sync(0xffffffffu, rr, o);
            ss += __shfl_xor_sync(0xffffffffu, ss, o);
        }
        if ((t & 31) == 0) { s_red[t >> 5] = rr; s_red2[t >> 5] = ss; }
        __syncthreads();
        if (t == 0) {
            float R = 0.f, S = 0.f;
#pragma unroll
            for (int i = 0; i < 8; i++) { R += s_red[i]; S += s_red2[i]; }
            float recon = S * (1.0f / ((float)BATCH * OUT_F));
            float reg   = 0.001f * R * (1.0f / ((float)IN_F * (float)BITS));
            if (out_size > 0) out[0] = recon + reg;
            if (out_size > 1) out[1] = recon;
            if (out_size > 2) out[2] = reg;
            g_ticket = 0;
        }
    }
}

// ---------------- launch ----------------
extern "C" void kernel_launch(void* const* d_in, const int* in_sizes, int n_in,
                              void* d_out, int out_size) {
    const float* latent   = (const float*)d_in[0];
    const float* true_sum = (const float*)d_in[1];
    const float* weight   = (const float*)d_in[2];

    static int smem_set = 0;
    if (!smem_set) {
        cudaFuncSetAttribute(k_gemm_loss, cudaFuncAttributeMaxDynamicSharedMemorySize,
                             DSMEM_BYTES);
        smem_set = 1;
    }

    k_pre<<<4096, 256>>>(weight, latent);
    k_gemm_loss<<<dim3(GX, GY), 256, DSMEM_BYTES>>>(true_sum, (float*)d_out, out_size);
}